// round 1
// baseline (speedup 1.0000x reference)
#include <cuda_runtime.h>
#include <math.h>

// ---------------------------------------------------------------------------
// CrossModalAttention: B=4, S=2048, H=2048
//   q_rot = RoPE(query); k_rot = RoPE(key)
//   q = q_rot @ Wq^T + bq ; k = k_rot @ Wk^T + bk ; v = value @ Wv^T + bv
//   scores = softmax(q @ k^T / sqrt(H)) ; ctx = scores @ v
//   out = ctx @ Wo^T + bo
// ---------------------------------------------------------------------------

constexpr int Bb = 4;
constexpr int Ss = 2048;
constexpr int Hh = 2048;
constexpr long BSH = (long)Bb * Ss * Hh;   // 16,777,216
constexpr long BSS = (long)Bb * Ss * Ss;   // 16,777,216

// Scratch (device globals: no allocations allowed)
__device__ float g_qrot[BSH];
__device__ float g_krot[BSH];
__device__ float g_q[BSH];
__device__ float g_k[BSH];
__device__ float g_v[BSH];
__device__ float g_scores[BSS];
__device__ float g_ctx[BSH];

// ---------------------------------------------------------------------------
// RoPE: out[b,s,d] = x[b,s,d]*cos(s*invf(d%1024)) + rot(x)[d]*sin(...)
// rot(x)[d] = -x[d+1024] (d<1024) else x[d-1024]
// invf(j) = 10000^(-j/1024), computed in fp32 like the reference.
// ---------------------------------------------------------------------------
__global__ void rope_kernel(const float* __restrict__ q,
                            const float* __restrict__ k,
                            float* __restrict__ qo,
                            float* __restrict__ ko) {
    long idx = (long)blockIdx.x * blockDim.x + threadIdx.x;
    if (idx >= BSH) return;
    int d = (int)(idx % Hh);
    int s = (int)((idx / Hh) % Ss);
    int j = d & (Hh / 2 - 1);                       // d % 1024
    float invf = powf(10000.0f, -(float)j * (1.0f / (Hh / 2)));
    float ang = (float)s * invf;
    float sn, cs;
    sincosf(ang, &sn, &cs);

    long other = (d < Hh / 2) ? idx + Hh / 2 : idx - Hh / 2;
    float sgn = (d < Hh / 2) ? -1.0f : 1.0f;

    float qv = q[idx], qr = sgn * q[other];
    float kv = k[idx], kr = sgn * k[other];
    qo[idx] = qv * cs + qr * sn;
    ko[idx] = kv * cs + kr * sn;
}

// ---------------------------------------------------------------------------
// Tiled fp32 GEMM, 128x128x8, 256 threads, 8x8 per-thread microtile.
// TRANSB=true : C[m,n] = alpha * dot(A[m,:], B[n,:])  (+ bias[n])   (NT)
// TRANSB=false: C[m,n] = alpha * sum_k A[m,k]*B[k,n]  (+ bias[n])   (NN)
// Batched via blockIdx.z with explicit strides. All dims multiples of 128/8.
// ---------------------------------------------------------------------------
template <bool TRANSB, bool BIAS>
__global__ __launch_bounds__(256, 2)
void gemm_kernel(const float* __restrict__ A,
                 const float* __restrict__ Bm,
                 const float* __restrict__ bias,
                 float* __restrict__ C,
                 int M, int N, int K,
                 long strideA, long strideB, long strideC,
                 float alpha) {
    constexpr int BM = 128, BN = 128, BK = 8, TM = 8, TN = 8;
    A  += (long)blockIdx.z * strideA;
    Bm += (long)blockIdx.z * strideB;
    C  += (long)blockIdx.z * strideC;

    __shared__ float As[BK][BM];
    __shared__ float Bs[BK][BN];

    const int tid  = threadIdx.x;
    const int row0 = blockIdx.y * BM;
    const int col0 = blockIdx.x * BN;
    const int tr = (tid / 16) * TM;   // 0..120
    const int tc = (tid % 16) * TN;   // 0..120

    // A tile loader: 128 rows x 8 k, one float4 per thread
    const int aRow  = tid >> 1;        // 0..127
    const int aCol4 = (tid & 1) * 4;   // 0 or 4
    // NN B tile loader: 8 k-rows x 128 cols
    const int bRow  = tid >> 5;        // 0..7
    const int bCol4 = (tid & 31) * 4;  // 0..124

    float acc[TM][TN];
#pragma unroll
    for (int i = 0; i < TM; i++)
#pragma unroll
        for (int j = 0; j < TN; j++) acc[i][j] = 0.0f;

    for (int k0 = 0; k0 < K; k0 += BK) {
        float4 av = *(const float4*)&A[(long)(row0 + aRow) * K + k0 + aCol4];
        As[aCol4 + 0][aRow] = av.x;
        As[aCol4 + 1][aRow] = av.y;
        As[aCol4 + 2][aRow] = av.z;
        As[aCol4 + 3][aRow] = av.w;
        if (TRANSB) {
            float4 bv = *(const float4*)&Bm[(long)(col0 + aRow) * K + k0 + aCol4];
            Bs[aCol4 + 0][aRow] = bv.x;
            Bs[aCol4 + 1][aRow] = bv.y;
            Bs[aCol4 + 2][aRow] = bv.z;
            Bs[aCol4 + 3][aRow] = bv.w;
        } else {
            float4 bv = *(const float4*)&Bm[(long)(k0 + bRow) * N + col0 + bCol4];
            *(float4*)&Bs[bRow][bCol4] = bv;
        }
        __syncthreads();

#pragma unroll
        for (int k = 0; k < BK; k++) {
            float ra[TM], rb[TN];
            *(float4*)&ra[0] = *(const float4*)&As[k][tr];
            *(float4*)&ra[4] = *(const float4*)&As[k][tr + 4];
            *(float4*)&rb[0] = *(const float4*)&Bs[k][tc];
            *(float4*)&rb[4] = *(const float4*)&Bs[k][tc + 4];
#pragma unroll
            for (int i = 0; i < TM; i++)
#pragma unroll
                for (int j = 0; j < TN; j++)
                    acc[i][j] = fmaf(ra[i], rb[j], acc[i][j]);
        }
        __syncthreads();
    }

    // Epilogue
#pragma unroll
    for (int i = 0; i < TM; i++) {
        long crow = (long)(row0 + tr + i) * N + col0 + tc;
#pragma unroll
        for (int j = 0; j < TN; j += 4) {
            float4 o;
            o.x = acc[i][j + 0] * alpha;
            o.y = acc[i][j + 1] * alpha;
            o.z = acc[i][j + 2] * alpha;
            o.w = acc[i][j + 3] * alpha;
            if (BIAS) {
                o.x += bias[col0 + tc + j + 0];
                o.y += bias[col0 + tc + j + 1];
                o.z += bias[col0 + tc + j + 2];
                o.w += bias[col0 + tc + j + 3];
            }
            *(float4*)&C[crow + j] = o;
        }
    }
}

// ---------------------------------------------------------------------------
// Row softmax over S=2048 columns, one block (256 threads) per row, in place.
// ---------------------------------------------------------------------------
__global__ void softmax_kernel(float* __restrict__ scores) {
    __shared__ float red[8];
    long row = blockIdx.x;
    float* p = scores + row * Ss;
    int tid = threadIdx.x;
    int lane = tid & 31, warp = tid >> 5;

    float m = -INFINITY;
    for (int c = tid; c < Ss; c += 256) m = fmaxf(m, p[c]);
#pragma unroll
    for (int o = 16; o > 0; o >>= 1) m = fmaxf(m, __shfl_xor_sync(0xffffffffu, m, o));
    if (lane == 0) red[warp] = m;
    __syncthreads();
    m = red[lane & 7];
#pragma unroll
    for (int o = 4; o > 0; o >>= 1) m = fmaxf(m, __shfl_xor_sync(0xffffffffu, m, o));

    float sum = 0.0f;
    for (int c = tid; c < Ss; c += 256) {
        float e = expf(p[c] - m);
        p[c] = e;
        sum += e;
    }
#pragma unroll
    for (int o = 16; o > 0; o >>= 1) sum += __shfl_xor_sync(0xffffffffu, sum, o);
    __syncthreads();
    if (lane == 0) red[warp] = sum;
    __syncthreads();
    sum = red[lane & 7];
#pragma unroll
    for (int o = 4; o > 0; o >>= 1) sum += __shfl_xor_sync(0xffffffffu, sum, o);
    float inv = 1.0f / sum;

    for (int c = tid; c < Ss; c += 256) p[c] *= inv;
}

// ---------------------------------------------------------------------------
extern "C" void kernel_launch(void* const* d_in, const int* in_sizes, int n_in,
                              void* d_out, int out_size) {
    const float* query = (const float*)d_in[0];
    const float* key   = (const float*)d_in[1];
    const float* value = (const float*)d_in[2];
    const float* Wq = (const float*)d_in[3];
    const float* bq = (const float*)d_in[4];
    const float* Wk = (const float*)d_in[5];
    const float* bk = (const float*)d_in[6];
    const float* Wv = (const float*)d_in[7];
    const float* bv = (const float*)d_in[8];
    const float* Wo = (const float*)d_in[9];
    const float* bo = (const float*)d_in[10];
    float* out = (float*)d_out;

    float *qrot, *krot, *q, *k, *v, *scores, *ctx;
    cudaGetSymbolAddress((void**)&qrot,   g_qrot);
    cudaGetSymbolAddress((void**)&krot,   g_krot);
    cudaGetSymbolAddress((void**)&q,      g_q);
    cudaGetSymbolAddress((void**)&k,      g_k);
    cudaGetSymbolAddress((void**)&v,      g_v);
    cudaGetSymbolAddress((void**)&scores, g_scores);
    cudaGetSymbolAddress((void**)&ctx,    g_ctx);

    const int M = Bb * Ss;  // 8192
    const float scale = 1.0f / sqrtf((float)Hh);

    // 1. RoPE
    rope_kernel<<<(int)((BSH + 255) / 256), 256>>>(query, key, qrot, krot);

    // 2-4. Projections: [8192,2048] x [2048,2048]^T + bias
    dim3 gProj(Hh / 128, M / 128, 1);
    gemm_kernel<true, true><<<gProj, 256>>>(qrot, Wq, bq, q, M, Hh, Hh, 0, 0, 0, 1.0f);
    gemm_kernel<true, true><<<gProj, 256>>>(krot, Wk, bk, k, M, Hh, Hh, 0, 0, 0, 1.0f);
    gemm_kernel<true, true><<<gProj, 256>>>(value, Wv, bv, v, M, Hh, Hh, 0, 0, 0, 1.0f);

    // 5. scores = q @ k^T * scale (batched over B)
    dim3 gAttn(Ss / 128, Ss / 128, Bb);
    gemm_kernel<true, false><<<gAttn, 256>>>(q, k, nullptr, scores,
                                             Ss, Ss, Hh,
                                             (long)Ss * Hh, (long)Ss * Hh, (long)Ss * Ss,
                                             scale);

    // 6. softmax rows
    softmax_kernel<<<Bb * Ss, 256>>>(scores);

    // 7. ctx = probs @ v (NN, batched)
    gemm_kernel<false, false><<<gAttn, 256>>>(scores, v, nullptr, ctx,
                                              Ss, Hh, Ss,
                                              (long)Ss * Ss, (long)Ss * Hh, (long)Ss * Hh,
                                              1.0f);

    // 8. out = ctx @ Wo^T + bo
    gemm_kernel<true, true><<<gProj, 256>>>(ctx, Wo, bo, out, M, Hh, Hh, 0, 0, 0, 1.0f);
}

// round 2
// speedup vs baseline: 2.1917x; 2.1917x over previous
#include <cuda_runtime.h>
#include <cuda_bf16.h>
#include <math.h>

typedef __nv_bfloat16 bf16;

// ---------------------------------------------------------------------------
// CrossModalAttention B=4, S=2048, H=2048 — split-bf16 tensor-core pipeline.
// Every fp32 operand x is represented as hi(bf16)+lo(bf16); GEMMs compute
// hi*hi + hi*lo + lo*hi with fp32 accumulation (error ~2^-17, safe vs 1e-3).
// ---------------------------------------------------------------------------

constexpr int Bb = 4;
constexpr int Ss = 2048;
constexpr int Hh = 2048;
constexpr long BSH = (long)Bb * Ss * Hh;   // 16,777,216
constexpr long BSS = (long)Bb * Ss * Ss;   // 16,777,216
constexpr long WW  = (long)Hh * Hh;        // 4,194,304

// Scratch (device globals; no allocations allowed)
__device__ bf16 g_qr_h[BSH], g_qr_l[BSH], g_kr_h[BSH], g_kr_l[BSH];
__device__ bf16 g_vi_h[BSH], g_vi_l[BSH];
__device__ bf16 g_q_h[BSH],  g_q_l[BSH];
__device__ bf16 g_k_h[BSH],  g_k_l[BSH];
__device__ bf16 g_v_h[BSH],  g_v_l[BSH];
__device__ bf16 g_p_h[BSS],  g_p_l[BSS];
__device__ bf16 g_c_h[BSH],  g_c_l[BSH];
__device__ bf16 g_wq_h[WW], g_wq_l[WW], g_wk_h[WW], g_wk_l[WW];
__device__ bf16 g_wv_h[WW], g_wv_l[WW], g_wo_h[WW], g_wo_l[WW];
__device__ float g_scores[BSS];

__device__ __forceinline__ void split2(float x, bf16& hi, bf16& lo) {
    hi = __float2bfloat16(x);
    lo = __float2bfloat16(x - __bfloat162float(hi));
}

// ---------------------------------------------------------------------------
// RoPE + split (query, key -> rotated hi/lo bf16)
// ---------------------------------------------------------------------------
__global__ void rope_split_kernel(const float* __restrict__ q,
                                  const float* __restrict__ k,
                                  bf16* __restrict__ qh, bf16* __restrict__ ql,
                                  bf16* __restrict__ kh, bf16* __restrict__ kl) {
    long idx = (long)blockIdx.x * blockDim.x + threadIdx.x;
    if (idx >= BSH) return;
    int d = (int)(idx % Hh);
    int s = (int)((idx / Hh) % Ss);
    int j = d & (Hh / 2 - 1);
    float invf = powf(10000.0f, -(float)j * (1.0f / (Hh / 2)));
    float ang = (float)s * invf;
    float sn, cs;
    sincosf(ang, &sn, &cs);

    long other = (d < Hh / 2) ? idx + Hh / 2 : idx - Hh / 2;
    float sgn = (d < Hh / 2) ? -1.0f : 1.0f;

    float qv = q[idx] * cs + sgn * q[other] * sn;
    float kv = k[idx] * cs + sgn * k[other] * sn;
    split2(qv, qh[idx], ql[idx]);
    split2(kv, kh[idx], kl[idx]);
}

// generic fp32 -> hi/lo split
__global__ void split_kernel(const float* __restrict__ src,
                             bf16* __restrict__ hi, bf16* __restrict__ lo, long n) {
    long idx = (long)blockIdx.x * blockDim.x + threadIdx.x;
    if (idx >= n) return;
    split2(src[idx], hi[idx], lo[idx]);
}

// ---------------------------------------------------------------------------
// mma.sync m16n8k16 bf16 (fp32 acc), documented lane layout.
// ---------------------------------------------------------------------------
__device__ __forceinline__ void mma16816(float* d, const unsigned* a, const unsigned* b) {
    asm volatile(
        "mma.sync.aligned.m16n8k16.row.col.f32.bf16.bf16.f32 "
        "{%0,%1,%2,%3}, {%4,%5,%6,%7}, {%8,%9}, {%0,%1,%2,%3};\n"
        : "+f"(d[0]), "+f"(d[1]), "+f"(d[2]), "+f"(d[3])
        : "r"(a[0]), "r"(a[1]), "r"(a[2]), "r"(a[3]), "r"(b[0]), "r"(b[1]));
}

// ---------------------------------------------------------------------------
// Split-bf16 GEMM. 128x128x32 block tile, 256 threads (8 warps, 4x2 grid),
// warp tile 32x64 (2 m16 x 8 n8). 3 mma products per position.
// TRANSB=true : C = A[M,K] * B[N,K]^T    (NT)
// TRANSB=false: C = A[M,K] * B[K,N]      (NN)
// SPLIT_OUT=true writes Ch/Cl bf16 pair, else writes Cf fp32.
// ---------------------------------------------------------------------------
template <bool TRANSB, bool BIAS, bool SPLIT_OUT>
__global__ __launch_bounds__(256, 2)
void bgemm(const bf16* __restrict__ Ah, const bf16* __restrict__ Al,
           const bf16* __restrict__ Bh, const bf16* __restrict__ Bl,
           const float* __restrict__ bias,
           float* __restrict__ Cf, bf16* __restrict__ Ch, bf16* __restrict__ Cl,
           int M, int N, int K,
           long sA, long sB, long sC, float alpha) {
    constexpr int BM = 128, BN = 128, BK = 32;
    constexpr int LDA = 40;    // A / NT-B smem stride (mult of 8)
    constexpr int LDBN = 136;  // NN-B smem stride (mult of 8)

    __shared__ bf16 sAh[BM * LDA], sAl[BM * LDA];
    __shared__ bf16 sBh[BN * LDA], sBl[BN * LDA];  // NN uses BK*LDBN=4352 <= 5120

    const int tid = threadIdx.x;
    const int warp = tid >> 5, lane = tid & 31;
    const int wm = warp >> 1, wn = warp & 1;       // 4 x 2 warps
    const int gid = lane >> 2, tig = lane & 3;

    const long batch = blockIdx.z;
    Ah += batch * sA; Al += batch * sA;
    Bh += batch * sB; Bl += batch * sB;

    const int row0 = blockIdx.y * BM;
    const int col0 = blockIdx.x * BN;

    float acc[2][8][4];
#pragma unroll
    for (int i = 0; i < 2; i++)
#pragma unroll
        for (int j = 0; j < 8; j++)
#pragma unroll
            for (int t = 0; t < 4; t++) acc[i][j][t] = 0.0f;

    for (int k0 = 0; k0 < K; k0 += BK) {
        // A tile: 128 rows x 32 k, uint4 = 8 bf16 per load
#pragma unroll
        for (int it = 0; it < 2; it++) {
            int idx = tid + it * 256;          // 0..511
            int r = idx >> 2, cg = (idx & 3) * 8;
            long goff = (long)(row0 + r) * K + k0 + cg;
            *(uint4*)&sAh[r * LDA + cg] = *(const uint4*)&Ah[goff];
            *(uint4*)&sAl[r * LDA + cg] = *(const uint4*)&Al[goff];
        }
        if (TRANSB) {
            // B tile: rows are output cols, [BN][BK]
#pragma unroll
            for (int it = 0; it < 2; it++) {
                int idx = tid + it * 256;
                int r = idx >> 2, cg = (idx & 3) * 8;
                long goff = (long)(col0 + r) * K + k0 + cg;
                *(uint4*)&sBh[r * LDA + cg] = *(const uint4*)&Bh[goff];
                *(uint4*)&sBl[r * LDA + cg] = *(const uint4*)&Bl[goff];
            }
        } else {
            // B tile: [BK][BN]
#pragma unroll
            for (int it = 0; it < 2; it++) {
                int idx = tid + it * 256;
                int r = idx >> 4, cg = (idx & 15) * 8;
                long goff = (long)(k0 + r) * N + col0 + cg;
                *(uint4*)&sBh[r * LDBN + cg] = *(const uint4*)&Bh[goff];
                *(uint4*)&sBl[r * LDBN + cg] = *(const uint4*)&Bl[goff];
            }
        }
        __syncthreads();

#pragma unroll
        for (int ks = 0; ks < BK; ks += 16) {
            unsigned ah[2][4], al[2][4];
#pragma unroll
            for (int im = 0; im < 2; im++) {
                int ar = wm * 32 + im * 16;
                ah[im][0] = *(const unsigned*)&sAh[(ar + gid) * LDA + ks + 2 * tig];
                ah[im][1] = *(const unsigned*)&sAh[(ar + gid + 8) * LDA + ks + 2 * tig];
                ah[im][2] = *(const unsigned*)&sAh[(ar + gid) * LDA + ks + 8 + 2 * tig];
                ah[im][3] = *(const unsigned*)&sAh[(ar + gid + 8) * LDA + ks + 8 + 2 * tig];
                al[im][0] = *(const unsigned*)&sAl[(ar + gid) * LDA + ks + 2 * tig];
                al[im][1] = *(const unsigned*)&sAl[(ar + gid + 8) * LDA + ks + 2 * tig];
                al[im][2] = *(const unsigned*)&sAl[(ar + gid) * LDA + ks + 8 + 2 * tig];
                al[im][3] = *(const unsigned*)&sAl[(ar + gid + 8) * LDA + ks + 8 + 2 * tig];
            }
#pragma unroll
            for (int jn = 0; jn < 8; jn++) {
                int bc = wn * 64 + jn * 8;
                unsigned bh[2], bl[2];
                if (TRANSB) {
                    bh[0] = *(const unsigned*)&sBh[(bc + gid) * LDA + ks + 2 * tig];
                    bh[1] = *(const unsigned*)&sBh[(bc + gid) * LDA + ks + 8 + 2 * tig];
                    bl[0] = *(const unsigned*)&sBl[(bc + gid) * LDA + ks + 2 * tig];
                    bl[1] = *(const unsigned*)&sBl[(bc + gid) * LDA + ks + 8 + 2 * tig];
                } else {
                    __nv_bfloat162 t0, t1;
                    t0.x = sBh[(ks + 2 * tig) * LDBN + bc + gid];
                    t0.y = sBh[(ks + 2 * tig + 1) * LDBN + bc + gid];
                    t1.x = sBh[(ks + 2 * tig + 8) * LDBN + bc + gid];
                    t1.y = sBh[(ks + 2 * tig + 9) * LDBN + bc + gid];
                    bh[0] = *(unsigned*)&t0; bh[1] = *(unsigned*)&t1;
                    t0.x = sBl[(ks + 2 * tig) * LDBN + bc + gid];
                    t0.y = sBl[(ks + 2 * tig + 1) * LDBN + bc + gid];
                    t1.x = sBl[(ks + 2 * tig + 8) * LDBN + bc + gid];
                    t1.y = sBl[(ks + 2 * tig + 9) * LDBN + bc + gid];
                    bl[0] = *(unsigned*)&t0; bl[1] = *(unsigned*)&t1;
                }
#pragma unroll
                for (int im = 0; im < 2; im++) {
                    mma16816(acc[im][jn], ah[im], bh);
                    mma16816(acc[im][jn], ah[im], bl);
                    mma16816(acc[im][jn], al[im], bh);
                }
            }
        }
        __syncthreads();
    }

    // Epilogue: c0:(g,2t) c1:(g,2t+1) c2:(g+8,2t) c3:(g+8,2t+1)
    const long cbase = batch * sC;
#pragma unroll
    for (int im = 0; im < 2; im++) {
#pragma unroll
        for (int jn = 0; jn < 8; jn++) {
            int r = row0 + wm * 32 + im * 16 + gid;
            int c = col0 + wn * 64 + jn * 8 + 2 * tig;
            float b0 = 0.f, b1 = 0.f;
            if (BIAS) { b0 = bias[c]; b1 = bias[c + 1]; }
#pragma unroll
            for (int half = 0; half < 2; half++) {
                int rr = r + half * 8;
                float v0 = acc[im][jn][half * 2 + 0] * alpha + b0;
                float v1 = acc[im][jn][half * 2 + 1] * alpha + b1;
                long off = cbase + (long)rr * N + c;
                if (SPLIT_OUT) {
                    __nv_bfloat162 h2, l2;
                    split2(v0, h2.x, l2.x);
                    split2(v1, h2.y, l2.y);
                    *(__nv_bfloat162*)&Ch[off] = h2;
                    *(__nv_bfloat162*)&Cl[off] = l2;
                } else {
                    float2 o; o.x = v0; o.y = v1;
                    *(float2*)&Cf[off] = o;
                }
            }
        }
    }
}

// ---------------------------------------------------------------------------
// Row softmax over S columns; writes probs as hi/lo bf16.
// ---------------------------------------------------------------------------
__global__ void softmax_split_kernel(const float* __restrict__ scores,
                                     bf16* __restrict__ ph, bf16* __restrict__ pl) {
    __shared__ float red[8];
    long row = blockIdx.x;
    const float* p = scores + row * Ss;
    int tid = threadIdx.x;
    int lane = tid & 31, warp = tid >> 5;

    float m = -INFINITY;
    for (int c = tid; c < Ss; c += 256) m = fmaxf(m, p[c]);
#pragma unroll
    for (int o = 16; o > 0; o >>= 1) m = fmaxf(m, __shfl_xor_sync(0xffffffffu, m, o));
    if (lane == 0) red[warp] = m;
    __syncthreads();
    m = red[lane & 7];
#pragma unroll
    for (int o = 4; o > 0; o >>= 1) m = fmaxf(m, __shfl_xor_sync(0xffffffffu, m, o));

    float sum = 0.0f;
    for (int c = tid; c < Ss; c += 256) sum += expf(p[c] - m);
#pragma unroll
    for (int o = 16; o > 0; o >>= 1) sum += __shfl_xor_sync(0xffffffffu, sum, o);
    __syncthreads();
    if (lane == 0) red[warp] = sum;
    __syncthreads();
    sum = red[lane & 7];
#pragma unroll
    for (int o = 4; o > 0; o >>= 1) sum += __shfl_xor_sync(0xffffffffu, sum, o);
    float inv = 1.0f / sum;

    for (int c = tid; c < Ss; c += 256) {
        float e = expf(p[c] - m) * inv;
        split2(e, ph[row * Ss + c], pl[row * Ss + c]);
    }
}

// ---------------------------------------------------------------------------
extern "C" void kernel_launch(void* const* d_in, const int* in_sizes, int n_in,
                              void* d_out, int out_size) {
    const float* query = (const float*)d_in[0];
    const float* key   = (const float*)d_in[1];
    const float* value = (const float*)d_in[2];
    const float* Wq = (const float*)d_in[3];
    const float* bq = (const float*)d_in[4];
    const float* Wk = (const float*)d_in[5];
    const float* bk = (const float*)d_in[6];
    const float* Wv = (const float*)d_in[7];
    const float* bv = (const float*)d_in[8];
    const float* Wo = (const float*)d_in[9];
    const float* bo = (const float*)d_in[10];
    float* out = (float*)d_out;

    bf16 *qrh, *qrl, *krh, *krl, *vih, *vil;
    bf16 *qh, *ql, *kh, *kl, *vh, *vl, *ph, *pl, *ch, *cl;
    bf16 *wqh, *wql, *wkh, *wkl, *wvh, *wvl, *woh, *wol;
    float* scores;
    cudaGetSymbolAddress((void**)&qrh, g_qr_h); cudaGetSymbolAddress((void**)&qrl, g_qr_l);
    cudaGetSymbolAddress((void**)&krh, g_kr_h); cudaGetSymbolAddress((void**)&krl, g_kr_l);
    cudaGetSymbolAddress((void**)&vih, g_vi_h); cudaGetSymbolAddress((void**)&vil, g_vi_l);
    cudaGetSymbolAddress((void**)&qh,  g_q_h);  cudaGetSymbolAddress((void**)&ql,  g_q_l);
    cudaGetSymbolAddress((void**)&kh,  g_k_h);  cudaGetSymbolAddress((void**)&kl,  g_k_l);
    cudaGetSymbolAddress((void**)&vh,  g_v_h);  cudaGetSymbolAddress((void**)&vl,  g_v_l);
    cudaGetSymbolAddress((void**)&ph,  g_p_h);  cudaGetSymbolAddress((void**)&pl,  g_p_l);
    cudaGetSymbolAddress((void**)&ch,  g_c_h);  cudaGetSymbolAddress((void**)&cl,  g_c_l);
    cudaGetSymbolAddress((void**)&wqh, g_wq_h); cudaGetSymbolAddress((void**)&wql, g_wq_l);
    cudaGetSymbolAddress((void**)&wkh, g_wk_h); cudaGetSymbolAddress((void**)&wkl, g_wk_l);
    cudaGetSymbolAddress((void**)&wvh, g_wv_h); cudaGetSymbolAddress((void**)&wvl, g_wv_l);
    cudaGetSymbolAddress((void**)&woh, g_wo_h); cudaGetSymbolAddress((void**)&wol, g_wo_l);
    cudaGetSymbolAddress((void**)&scores, g_scores);

    const int M = Bb * Ss;  // 8192
    const float scale = 1.0f / sqrtf((float)Hh);

    // RoPE + split q,k ; split value + weights
    rope_split_kernel<<<(int)((BSH + 255) / 256), 256>>>(query, key, qrh, qrl, krh, krl);
    split_kernel<<<(int)((BSH + 255) / 256), 256>>>(value, vih, vil, BSH);
    split_kernel<<<(int)((WW + 255) / 256), 256>>>(Wq, wqh, wql, WW);
    split_kernel<<<(int)((WW + 255) / 256), 256>>>(Wk, wkh, wkl, WW);
    split_kernel<<<(int)((WW + 255) / 256), 256>>>(Wv, wvh, wvl, WW);
    split_kernel<<<(int)((WW + 255) / 256), 256>>>(Wo, woh, wol, WW);

    // Projections (NT, bias, split output)
    dim3 gProj(Hh / 128, M / 128, 1);
    bgemm<true, true, true><<<gProj, 256>>>(qrh, qrl, wqh, wql, bq,
                                            nullptr, qh, ql, M, Hh, Hh, 0, 0, 0, 1.0f);
    bgemm<true, true, true><<<gProj, 256>>>(krh, krl, wkh, wkl, bk,
                                            nullptr, kh, kl, M, Hh, Hh, 0, 0, 0, 1.0f);
    bgemm<true, true, true><<<gProj, 256>>>(vih, vil, wvh, wvl, bv,
                                            nullptr, vh, vl, M, Hh, Hh, 0, 0, 0, 1.0f);

    // scores = q @ k^T * scale (NT, batched, fp32 out)
    dim3 gAttn(Ss / 128, Ss / 128, Bb);
    bgemm<true, false, false><<<gAttn, 256>>>(qh, ql, kh, kl, nullptr,
                                              scores, nullptr, nullptr,
                                              Ss, Ss, Hh,
                                              (long)Ss * Hh, (long)Ss * Hh, (long)Ss * Ss,
                                              scale);

    // softmax -> probs hi/lo
    softmax_split_kernel<<<Bb * Ss, 256>>>(scores, ph, pl);

    // ctx = probs @ v (NN, batched, split out)
    bgemm<false, false, true><<<gAttn, 256>>>(ph, pl, vh, vl, nullptr,
                                              nullptr, ch, cl,
                                              Ss, Hh, Ss,
                                              (long)Ss * Ss, (long)Ss * Hh, (long)Ss * Hh,
                                              1.0f);

    // out = ctx @ Wo^T + bo (NT, fp32 out)
    bgemm<true, true, false><<<gProj, 256>>>(ch, cl, woh, wol, bo,
                                             out, nullptr, nullptr,
                                             M, Hh, Hh, 0, 0, 0, 1.0f);
}

// round 5
// speedup vs baseline: 2.6512x; 1.2096x over previous
#include <cuda_runtime.h>
#include <cuda_bf16.h>
#include <math.h>

typedef __nv_bfloat16 bf16;

// ---------------------------------------------------------------------------
// CrossModalAttention B=4, S=2048, H=2048 — split-bf16 tensor-core pipeline
// with cp.async double-buffered GEMM mainloops.
// ---------------------------------------------------------------------------

constexpr int Bb = 4;
constexpr int Ss = 2048;
constexpr int Hh = 2048;
constexpr long BSH = (long)Bb * Ss * Hh;   // 16,777,216
constexpr long BSS = (long)Bb * Ss * Ss;   // 16,777,216
constexpr long WW  = (long)Hh * Hh;        // 4,194,304

// Scratch (device globals; no allocations allowed)
__device__ bf16 g_qr_h[BSH], g_qr_l[BSH], g_kr_h[BSH], g_kr_l[BSH];
__device__ bf16 g_vi_h[BSH], g_vi_l[BSH];
__device__ bf16 g_q_h[BSH],  g_q_l[BSH];
__device__ bf16 g_k_h[BSH],  g_k_l[BSH];
__device__ bf16 g_v_h[BSH],  g_v_l[BSH];
__device__ bf16 g_p_h[BSS],  g_p_l[BSS];
__device__ bf16 g_c_h[BSH],  g_c_l[BSH];
__device__ bf16 g_wq_h[WW], g_wq_l[WW], g_wk_h[WW], g_wk_l[WW];
__device__ bf16 g_wv_h[WW], g_wv_l[WW], g_wo_h[WW], g_wo_l[WW];
__device__ float g_scores[BSS];
__device__ float g_cos[(long)Ss * (Hh / 2)];
__device__ float g_sin[(long)Ss * (Hh / 2)];

__device__ __forceinline__ void split2(float x, bf16& hi, bf16& lo) {
    hi = __float2bfloat16(x);
    lo = __float2bfloat16(x - __bfloat162float(hi));
}

__device__ __forceinline__ void store_split4(bf16* hi, bf16* lo, long idx, const float* v) {
    __nv_bfloat162 h0, h1, l0, l1;
    split2(v[0], h0.x, l0.x); split2(v[1], h0.y, l0.y);
    split2(v[2], h1.x, l1.x); split2(v[3], h1.y, l1.y);
    *(__nv_bfloat162*)&hi[idx]     = h0;
    *(__nv_bfloat162*)&hi[idx + 2] = h1;
    *(__nv_bfloat162*)&lo[idx]     = l0;
    *(__nv_bfloat162*)&lo[idx + 2] = l1;
}

__device__ __forceinline__ void cp16(void* sdst, const void* gsrc) {
    unsigned s = (unsigned)__cvta_generic_to_shared(sdst);
    asm volatile("cp.async.cg.shared.global [%0], [%1], 16;\n" :: "r"(s), "l"(gsrc));
}

// ---------------------------------------------------------------------------
// RoPE tables: cos/sin[s, j] (fp32, same powf/sincosf math as before)
// ---------------------------------------------------------------------------
__global__ void rope_tables_kernel(float* __restrict__ ct, float* __restrict__ st) {
    long idx = (long)blockIdx.x * blockDim.x + threadIdx.x;
    if (idx >= (long)Ss * (Hh / 2)) return;
    int j = (int)(idx & (Hh / 2 - 1));
    int s = (int)(idx >> 10);
    float invf = powf(10000.0f, -(float)j * (1.0f / (Hh / 2)));
    float ang = (float)s * invf;
    float sn, cs;
    sincosf(ang, &sn, &cs);
    ct[idx] = cs;
    st[idx] = sn;
}

// ---------------------------------------------------------------------------
// RoPE + split (vectorized x4)
// ---------------------------------------------------------------------------
__global__ void rope_split_kernel(const float* __restrict__ q,
                                  const float* __restrict__ k,
                                  const float* __restrict__ ct,
                                  const float* __restrict__ st,
                                  bf16* __restrict__ qh, bf16* __restrict__ ql,
                                  bf16* __restrict__ kh, bf16* __restrict__ kl) {
    long i4 = (long)blockIdx.x * blockDim.x + threadIdx.x;
    if (i4 >= BSH / 4) return;
    long idx = i4 * 4;
    int d = (int)(idx % Hh);
    int s = (int)((idx / Hh) % Ss);
    int j = d & (Hh / 2 - 1);
    bool low = d < Hh / 2;
    long o4 = low ? i4 + (Hh / 8) : i4 - (Hh / 8);
    float sgn = low ? -1.0f : 1.0f;

    float4 qv = ((const float4*)q)[i4];
    float4 qo = ((const float4*)q)[o4];
    float4 kv = ((const float4*)k)[i4];
    float4 ko = ((const float4*)k)[o4];
    float4 c4 = *(const float4*)&ct[(long)s * (Hh / 2) + j];
    float4 s4 = *(const float4*)&st[(long)s * (Hh / 2) + j];

    float qr[4], kr[4];
    qr[0] = qv.x * c4.x + sgn * qo.x * s4.x;
    qr[1] = qv.y * c4.y + sgn * qo.y * s4.y;
    qr[2] = qv.z * c4.z + sgn * qo.z * s4.z;
    qr[3] = qv.w * c4.w + sgn * qo.w * s4.w;
    kr[0] = kv.x * c4.x + sgn * ko.x * s4.x;
    kr[1] = kv.y * c4.y + sgn * ko.y * s4.y;
    kr[2] = kv.z * c4.z + sgn * ko.z * s4.z;
    kr[3] = kv.w * c4.w + sgn * ko.w * s4.w;

    store_split4(qh, ql, idx, qr);
    store_split4(kh, kl, idx, kr);
}

// generic fp32 -> hi/lo split (vectorized x4)
__global__ void split_kernel(const float* __restrict__ src,
                             bf16* __restrict__ hi, bf16* __restrict__ lo, long n4) {
    long i4 = (long)blockIdx.x * blockDim.x + threadIdx.x;
    if (i4 >= n4) return;
    float4 v4 = ((const float4*)src)[i4];
    float v[4] = {v4.x, v4.y, v4.z, v4.w};
    store_split4(hi, lo, i4 * 4, v);
}

// ---------------------------------------------------------------------------
// mma.sync m16n8k16 bf16 (fp32 acc)
// ---------------------------------------------------------------------------
__device__ __forceinline__ void mma16816(float* d, const unsigned* a, const unsigned* b) {
    asm volatile(
        "mma.sync.aligned.m16n8k16.row.col.f32.bf16.bf16.f32 "
        "{%0,%1,%2,%3}, {%4,%5,%6,%7}, {%8,%9}, {%0,%1,%2,%3};\n"
        : "+f"(d[0]), "+f"(d[1]), "+f"(d[2]), "+f"(d[3])
        : "r"(a[0]), "r"(a[1]), "r"(a[2]), "r"(a[3]), "r"(b[0]), "r"(b[1]));
}

// ---------------------------------------------------------------------------
// Split-bf16 GEMM, cp.async double-buffered. 128x128x32 tile, 256 threads,
// warp tile 32x64. 3 mma products per position (hh, hl, lh).
// ---------------------------------------------------------------------------
template <bool TRANSB, bool BIAS, bool SPLIT_OUT>
__global__ __launch_bounds__(256, 2)
void bgemm(const bf16* __restrict__ Ah, const bf16* __restrict__ Al,
           const bf16* __restrict__ Bh, const bf16* __restrict__ Bl,
           const float* __restrict__ bias,
           float* __restrict__ Cf, bf16* __restrict__ Ch, bf16* __restrict__ Cl,
           int M, int N, int K,
           long sA, long sB, long sC, float alpha) {
    constexpr int BM = 128, BN = 128, BK = 32;
    constexpr int LDA = 40;    // padded k-major stride
    constexpr int LDBN = 136;  // padded NN n-major stride
    constexpr int ASZ = BM * LDA;
    constexpr int BSZ = TRANSB ? BM * LDA : BK * LDBN;
    constexpr int STAGE = 2 * ASZ + 2 * BSZ;
    extern __shared__ bf16 smem[];

    const int tid = threadIdx.x;
    const int warp = tid >> 5, lane = tid & 31;
    const int wm = warp >> 1, wn = warp & 1;
    const int gid = lane >> 2, tig = lane & 3;

    const long batch = blockIdx.z;
    Ah += batch * sA; Al += batch * sA;
    Bh += batch * sB; Bl += batch * sB;

    const int row0 = blockIdx.y * BM;
    const int col0 = blockIdx.x * BN;

    const int lr = tid >> 2, lc = (tid & 3) * 8;   // A / NT-B loader
    const int nr = tid >> 4, nc = (tid & 15) * 8;  // NN-B loader

    auto prefetch = [&](int k0, bf16* st) {
        bf16* pAh = st;
        bf16* pAl = st + ASZ;
        bf16* pBh = st + 2 * ASZ;
        bf16* pBl = st + 2 * ASZ + BSZ;
#pragma unroll
        for (int it = 0; it < 2; it++) {
            int r = lr + it * 64;
            long g = (long)(row0 + r) * K + k0 + lc;
            cp16(&pAh[r * LDA + lc], &Ah[g]);
            cp16(&pAl[r * LDA + lc], &Al[g]);
        }
        if (TRANSB) {
#pragma unroll
            for (int it = 0; it < 2; it++) {
                int r = lr + it * 64;
                long g = (long)(col0 + r) * K + k0 + lc;
                cp16(&pBh[r * LDA + lc], &Bh[g]);
                cp16(&pBl[r * LDA + lc], &Bl[g]);
            }
        } else {
#pragma unroll
            for (int it = 0; it < 2; it++) {
                int r = nr + it * 16;
                long g = (long)(k0 + r) * N + col0 + nc;
                cp16(&pBh[r * LDBN + nc], &Bh[g]);
                cp16(&pBl[r * LDBN + nc], &Bl[g]);
            }
        }
        asm volatile("cp.async.commit_group;\n" ::: "memory");
    };

    float acc[2][8][4];
#pragma unroll
    for (int i = 0; i < 2; i++)
#pragma unroll
        for (int j = 0; j < 8; j++)
#pragma unroll
            for (int t = 0; t < 4; t++) acc[i][j][t] = 0.0f;

    const int nk = K / BK;
    prefetch(0, smem);

    for (int itk = 0; itk < nk; ++itk) {
        bf16* cur = smem + (itk & 1) * STAGE;
        bf16* nxt = smem + ((itk + 1) & 1) * STAGE;
        if (itk + 1 < nk) {
            prefetch((itk + 1) * BK, nxt);
            asm volatile("cp.async.wait_group 1;\n" ::: "memory");
        } else {
            asm volatile("cp.async.wait_group 0;\n" ::: "memory");
        }
        __syncthreads();

        bf16* sAh = cur;
        bf16* sAl = cur + ASZ;
        bf16* sBh = cur + 2 * ASZ;
        bf16* sBl = cur + 2 * ASZ + BSZ;

#pragma unroll
        for (int ks = 0; ks < BK; ks += 16) {
            unsigned ah[2][4], al[2][4];
#pragma unroll
            for (int im = 0; im < 2; im++) {
                int ar = wm * 32 + im * 16;
                ah[im][0] = *(const unsigned*)&sAh[(ar + gid) * LDA + ks + 2 * tig];
                ah[im][1] = *(const unsigned*)&sAh[(ar + gid + 8) * LDA + ks + 2 * tig];
                ah[im][2] = *(const unsigned*)&sAh[(ar + gid) * LDA + ks + 8 + 2 * tig];
                ah[im][3] = *(const unsigned*)&sAh[(ar + gid + 8) * LDA + ks + 8 + 2 * tig];
                al[im][0] = *(const unsigned*)&sAl[(ar + gid) * LDA + ks + 2 * tig];
                al[im][1] = *(const unsigned*)&sAl[(ar + gid + 8) * LDA + ks + 2 * tig];
                al[im][2] = *(const unsigned*)&sAl[(ar + gid) * LDA + ks + 8 + 2 * tig];
                al[im][3] = *(const unsigned*)&sAl[(ar + gid + 8) * LDA + ks + 8 + 2 * tig];
            }
#pragma unroll
            for (int jn = 0; jn < 8; jn++) {
                int bc = wn * 64 + jn * 8;
                unsigned bh[2], bl[2];
                if (TRANSB) {
                    bh[0] = *(const unsigned*)&sBh[(bc + gid) * LDA + ks + 2 * tig];
                    bh[1] = *(const unsigned*)&sBh[(bc + gid) * LDA + ks + 8 + 2 * tig];
                    bl[0] = *(const unsigned*)&sBl[(bc + gid) * LDA + ks + 2 * tig];
                    bl[1] = *(const unsigned*)&sBl[(bc + gid) * LDA + ks + 8 + 2 * tig];
                } else {
                    __nv_bfloat162 t0, t1;
                    t0.x = sBh[(ks + 2 * tig) * LDBN + bc + gid];
                    t0.y = sBh[(ks + 2 * tig + 1) * LDBN + bc + gid];
                    t1.x = sBh[(ks + 2 * tig + 8) * LDBN + bc + gid];
                    t1.y = sBh[(ks + 2 * tig + 9) * LDBN + bc + gid];
                    bh[0] = *(unsigned*)&t0; bh[1] = *(unsigned*)&t1;
                    t0.x = sBl[(ks + 2 * tig) * LDBN + bc + gid];
                    t0.y = sBl[(ks + 2 * tig + 1) * LDBN + bc + gid];
                    t1.x = sBl[(ks + 2 * tig + 8) * LDBN + bc + gid];
                    t1.y = sBl[(ks + 2 * tig + 9) * LDBN + bc + gid];
                    bl[0] = *(unsigned*)&t0; bl[1] = *(unsigned*)&t1;
                }
#pragma unroll
                for (int im = 0; im < 2; im++) {
                    mma16816(acc[im][jn], ah[im], bh);
                    mma16816(acc[im][jn], ah[im], bl);
                    mma16816(acc[im][jn], al[im], bh);
                }
            }
        }
        __syncthreads();
    }

    // Epilogue: c0:(g,2t) c1:(g,2t+1) c2:(g+8,2t) c3:(g+8,2t+1)
    const long cbase = batch * sC;
#pragma unroll
    for (int im = 0; im < 2; im++) {
#pragma unroll
        for (int jn = 0; jn < 8; jn++) {
            int r = row0 + wm * 32 + im * 16 + gid;
            int c = col0 + wn * 64 + jn * 8 + 2 * tig;
            float b0 = 0.f, b1 = 0.f;
            if (BIAS) { b0 = bias[c]; b1 = bias[c + 1]; }
#pragma unroll
            for (int half = 0; half < 2; half++) {
                int rr = r + half * 8;
                float v0 = acc[im][jn][half * 2 + 0] * alpha + b0;
                float v1 = acc[im][jn][half * 2 + 1] * alpha + b1;
                long off = cbase + (long)rr * N + c;
                if (SPLIT_OUT) {
                    __nv_bfloat162 h2, l2;
                    split2(v0, h2.x, l2.x);
                    split2(v1, h2.y, l2.y);
                    *(__nv_bfloat162*)&Ch[off] = h2;
                    *(__nv_bfloat162*)&Cl[off] = l2;
                } else {
                    float2 o; o.x = v0; o.y = v1;
                    *(float2*)&Cf[off] = o;
                }
            }
        }
    }
}

// ---------------------------------------------------------------------------
// Row softmax, row cached in registers (2048 cols, 256 thr, 8 vals/thr).
// ---------------------------------------------------------------------------
__global__ void softmax_split_kernel(const float* __restrict__ scores,
                                     bf16* __restrict__ ph, bf16* __restrict__ pl) {
    __shared__ float red[8];
    long row = blockIdx.x;
    const float4* p = (const float4*)(scores + row * Ss);
    int tid = threadIdx.x;
    int lane = tid & 31, warp = tid >> 5;

    float4 v0 = p[tid];
    float4 v1 = p[tid + 256];
    float x[8] = {v0.x, v0.y, v0.z, v0.w, v1.x, v1.y, v1.z, v1.w};

    float m = x[0];
#pragma unroll
    for (int i = 1; i < 8; i++) m = fmaxf(m, x[i]);
#pragma unroll
    for (int o = 16; o > 0; o >>= 1) m = fmaxf(m, __shfl_xor_sync(0xffffffffu, m, o));
    if (lane == 0) red[warp] = m;
    __syncthreads();
    m = red[lane & 7];
#pragma unroll
    for (int o = 4; o > 0; o >>= 1) m = fmaxf(m, __shfl_xor_sync(0xffffffffu, m, o));

    float e[8];
    float sum = 0.0f;
#pragma unroll
    for (int i = 0; i < 8; i++) { e[i] = expf(x[i] - m); sum += e[i]; }
#pragma unroll
    for (int o = 16; o > 0; o >>= 1) sum += __shfl_xor_sync(0xffffffffu, sum, o);
    __syncthreads();
    if (lane == 0) red[warp] = sum;
    __syncthreads();
    sum = red[lane & 7];
#pragma unroll
    for (int o = 4; o > 0; o >>= 1) sum += __shfl_xor_sync(0xffffffffu, sum, o);
    float inv = 1.0f / sum;

    float o0[4] = {e[0] * inv, e[1] * inv, e[2] * inv, e[3] * inv};
    float o1[4] = {e[4] * inv, e[5] * inv, e[6] * inv, e[7] * inv};
    store_split4(ph, pl, row * Ss + tid * 4, o0);
    store_split4(ph, pl, row * Ss + 1024 + tid * 4, o1);
}

// ---------------------------------------------------------------------------
extern "C" void kernel_launch(void* const* d_in, const int* in_sizes, int n_in,
                              void* d_out, int out_size) {
    const float* query = (const float*)d_in[0];
    const float* key   = (const float*)d_in[1];
    const float* value = (const float*)d_in[2];
    const float* Wq = (const float*)d_in[3];
    const float* bq = (const float*)d_in[4];
    const float* Wk = (const float*)d_in[5];
    const float* bk = (const float*)d_in[6];
    const float* Wv = (const float*)d_in[7];
    const float* bv = (const float*)d_in[8];
    const float* Wo = (const float*)d_in[9];
    const float* bo = (const float*)d_in[10];
    float* out = (float*)d_out;

    bf16 *qrh, *qrl, *krh, *krl, *vih, *vil;
    bf16 *qh, *ql, *kh, *kl, *vh, *vl, *ph, *pl, *ch, *cl;
    bf16 *wqh, *wql, *wkh, *wkl, *wvh, *wvl, *woh, *wol;
    float *scores, *ctab, *stab;
    cudaGetSymbolAddress((void**)&qrh, g_qr_h); cudaGetSymbolAddress((void**)&qrl, g_qr_l);
    cudaGetSymbolAddress((void**)&krh, g_kr_h); cudaGetSymbolAddress((void**)&krl, g_kr_l);
    cudaGetSymbolAddress((void**)&vih, g_vi_h); cudaGetSymbolAddress((void**)&vil, g_vi_l);
    cudaGetSymbolAddress((void**)&qh,  g_q_h);  cudaGetSymbolAddress((void**)&ql,  g_q_l);
    cudaGetSymbolAddress((void**)&kh,  g_k_h);  cudaGetSymbolAddress((void**)&kl,  g_k_l);
    cudaGetSymbolAddress((void**)&vh,  g_v_h);  cudaGetSymbolAddress((void**)&vl,  g_v_l);
    cudaGetSymbolAddress((void**)&ph,  g_p_h);  cudaGetSymbolAddress((void**)&pl,  g_p_l);
    cudaGetSymbolAddress((void**)&ch,  g_c_h);  cudaGetSymbolAddress((void**)&cl,  g_c_l);
    cudaGetSymbolAddress((void**)&wqh, g_wq_h); cudaGetSymbolAddress((void**)&wql, g_wq_l);
    cudaGetSymbolAddress((void**)&wkh, g_wk_h); cudaGetSymbolAddress((void**)&wkl, g_wk_l);
    cudaGetSymbolAddress((void**)&wvh, g_wv_h); cudaGetSymbolAddress((void**)&wvl, g_wv_l);
    cudaGetSymbolAddress((void**)&woh, g_wo_h); cudaGetSymbolAddress((void**)&wol, g_wo_l);
    cudaGetSymbolAddress((void**)&scores, g_scores);
    cudaGetSymbolAddress((void**)&ctab, g_cos);
    cudaGetSymbolAddress((void**)&stab, g_sin);

    // Opt-in dynamic smem (NT: 81920 B, NN: 75776 B per CTA)
    const int smemNT = 81920, smemNN = 75776;
    cudaFuncSetAttribute(bgemm<true,  true,  true >, cudaFuncAttributeMaxDynamicSharedMemorySize, smemNT);
    cudaFuncSetAttribute(bgemm<true,  false, false>, cudaFuncAttributeMaxDynamicSharedMemorySize, smemNT);
    cudaFuncSetAttribute(bgemm<true,  true,  false>, cudaFuncAttributeMaxDynamicSharedMemorySize, smemNT);
    cudaFuncSetAttribute(bgemm<false, false, true >, cudaFuncAttributeMaxDynamicSharedMemorySize, smemNN);

    const int M = Bb * Ss;  // 8192
    const float scale = 1.0f / sqrtf((float)Hh);

    // RoPE tables + RoPE/split + weight/value splits
    rope_tables_kernel<<<(int)((Ss * (Hh / 2) + 255) / 256), 256>>>(ctab, stab);
    rope_split_kernel<<<(int)((BSH / 4 + 255) / 256), 256>>>(query, key, ctab, stab,
                                                             qrh, qrl, krh, krl);
    split_kernel<<<(int)((BSH / 4 + 255) / 256), 256>>>(value, vih, vil, BSH / 4);
    split_kernel<<<(int)((WW / 4 + 255) / 256), 256>>>(Wq, wqh, wql, WW / 4);
    split_kernel<<<(int)((WW / 4 + 255) / 256), 256>>>(Wk, wkh, wkl, WW / 4);
    split_kernel<<<(int)((WW / 4 + 255) / 256), 256>>>(Wv, wvh, wvl, WW / 4);
    split_kernel<<<(int)((WW / 4 + 255) / 256), 256>>>(Wo, woh, wol, WW / 4);

    // Projections (NT, bias, split output)
    dim3 gProj(Hh / 128, M / 128, 1);
    bgemm<true, true, true><<<gProj, 256, smemNT>>>(qrh, qrl, wqh, wql, bq,
                                                    nullptr, qh, ql, M, Hh, Hh, 0, 0, 0, 1.0f);
    bgemm<true, true, true><<<gProj, 256, smemNT>>>(krh, krl, wkh, wkl, bk,
                                                    nullptr, kh, kl, M, Hh, Hh, 0, 0, 0, 1.0f);
    bgemm<true, true, true><<<gProj, 256, smemNT>>>(vih, vil, wvh, wvl, bv,
                                                    nullptr, vh, vl, M, Hh, Hh, 0, 0, 0, 1.0f);

    // scores = q @ k^T * scale (NT, batched, fp32 out)
    dim3 gAttn(Ss / 128, Ss / 128, Bb);
    bgemm<true, false, false><<<gAttn, 256, smemNT>>>(qh, ql, kh, kl, nullptr,
                                                      scores, nullptr, nullptr,
                                                      Ss, Ss, Hh,
                                                      (long)Ss * Hh, (long)Ss * Hh, (long)Ss * Ss,
                                                      scale);

    // softmax -> probs hi/lo
    softmax_split_kernel<<<Bb * Ss, 256>>>(scores, ph, pl);

    // ctx = probs @ v (NN, batched, split out)
    bgemm<false, false, true><<<gAttn, 256, smemNN>>>(ph, pl, vh, vl, nullptr,
                                                      nullptr, ch, cl,
                                                      Ss, Hh, Ss,
                                                      (long)Ss * Ss, (long)Ss * Hh, (long)Ss * Hh,
                                                      1.0f);

    // out = ctx @ Wo^T + bo (NT, fp32 out)
    bgemm<true, true, false><<<gProj, 256, smemNT>>>(ch, cl, woh, wol, bo,
                                                     out, nullptr, nullptr,
                                                     M, Hh, Hh, 0, 0, 0, 1.0f);
}